// round 15
// baseline (speedup 1.0000x reference)
#include <cuda_runtime.h>
#include <math.h>

#define Lr 1024
#define Br 32
#define Dr 256
#define LAMf 0.2f
#define NR (Lr*Br)

// Scratch (device globals, zero-initialized). Batch-major r = b*Lr + i.
__device__ float g_Kn[NR*5];     // K[i,d] * invS[i]
__device__ float g_En[NR];       // E[i]  * invS[i]

typedef unsigned long long u64;

__device__ __forceinline__ u64 ffma2(u64 a, u64 b, u64 c) {
    u64 d;
    asm("fma.rn.f32x2 %0, %1, %2, %3;" : "=l"(d) : "l"(a), "l"(b), "l"(c));
    return d;
}
__device__ __forceinline__ float unpack_sum(u64 a) {
    float2 f = *reinterpret_cast<float2*>(&a);
    return f.x + f.y;
}

// ---------------------------------------------------------------- band kernel
// 2048 batch-pure blocks x 512 threads; block = (batch b, 16 rows i0..i0+15).
// Phase 0: stage 20 y rows (i0-2..i0+17) into smem, coalesced (OOB rows -> 0).
// Phase 1: 20 y inverse norms from smem.
// Phase 2: warp w owns row i = i0+w: x via LDG, 5 dots + xx from smem y (LDS).
__global__ void __launch_bounds__(512) kband(const float* __restrict__ m1,
                                             const float* __restrict__ m2,
                                             const int* __restrict__ lengths) {
    __shared__ float4 sh_y[20*64];   // 20 rows x 256 floats = 20 KB
    __shared__ float  sh_invny[20];

    int tid  = threadIdx.x;
    int w    = tid >> 5, lane = tid & 31;
    int b    = blockIdx.x & 31;
    int i0   = (blockIdx.x >> 5) * 16;
    int l    = __ldg(lengths + b);
    int base = b * Lr;

    // ---- phase 0: cooperative y staging (1280 float4, 512 threads x 3) ----
    {
        const float4* m2f4 = (const float4*)m2;
        #pragma unroll
        for (int k = 0; k < 3; k++) {
            int idx = tid + k*512;
            if (idx < 20*64) {
                int row  = idx >> 6;
                int col  = idx & 63;
                int grow = i0 - 2 + row;
                float4 v = make_float4(0.f, 0.f, 0.f, 0.f);
                if (grow >= 0 && grow < l)
                    v = m2f4[(size_t)(grow*Br + b) * 64 + col];
                sh_y[idx] = v;
            }
        }
    }
    __syncthreads();

    // ---- phase 1: 20 y norms from smem (jobs w, w+16) ----
    {
        float ss[2];
        #pragma unroll
        for (int k = 0; k < 2; k++) {
            int job = w + k*16;
            float s = 0.0f;
            if (job < 20) {
                float4 a = sh_y[job*64 + lane];
                float4 c = sh_y[job*64 + lane + 32];
                s = a.x*a.x + a.y*a.y + a.z*a.z + a.w*a.w
                  + c.x*c.x + c.y*c.y + c.z*c.z + c.w*c.w;
            }
            ss[k] = s;
        }
        #pragma unroll
        for (int o = 16; o; o >>= 1) {
            #pragma unroll
            for (int k = 0; k < 2; k++) ss[k] += __shfl_xor_sync(0xffffffffu, ss[k], o);
        }
        if (lane == 0) {
            #pragma unroll
            for (int k = 0; k < 2; k++) {
                int job = w + k*16;
                if (job < 20)
                    sh_invny[job] = (ss[k] > 0.0f) ? (1.0f / fmaxf(sqrtf(ss[k]), 1e-5f)) : 0.0f;
            }
        }
    }
    __syncthreads();

    // ---- phase 2: warp w owns row i = i0 + w ----
    int i = i0 + w;
    if (i >= l) return;
    const ulonglong2* xp = (const ulonglong2*)(m1 + ((size_t)(i*Br + b)) * Dr);
    ulonglong2 xa = xp[lane], xb = xp[lane + 32];

    u64 pacc[6];
    pacc[0] = ffma2(xa.x, xa.x, 0ull);
    pacc[0] = ffma2(xa.y, xa.y, pacc[0]);
    pacc[0] = ffma2(xb.x, xb.x, pacc[0]);
    pacc[0] = ffma2(xb.y, xb.y, pacc[0]);
    #pragma unroll
    for (int d = 0; d < 5; d++) {
        // y row j = i+d-2 lives at smem row (w+d); OOB rows staged as zeros -> dot 0.
        const u64* yr = (const u64*)(sh_y + (w + d) * 64);
        u64 acc = ffma2(xa.x, yr[2*lane],        0ull);
        acc     = ffma2(xa.y, yr[2*lane + 1],    acc);
        acc     = ffma2(xb.x, yr[2*(lane+32)],   acc);
        acc     = ffma2(xb.y, yr[2*(lane+32)+1], acc);
        pacc[d + 1] = acc;
    }
    float s[6];
    #pragma unroll
    for (int q = 0; q < 6; q++) s[q] = unpack_sum(pacc[q]);
    #pragma unroll
    for (int o = 16; o; o >>= 1) {
        #pragma unroll
        for (int q = 0; q < 6; q++) s[q] += __shfl_xor_sync(0xffffffffu, s[q], o);
    }

    // ---- lane-parallel tail: lanes 0-4 handle d = lane ----
    float invnx = 1.0f / fmaxf(sqrtf(s[0]), 1e-5f);
    int d = lane;
    float Kv = 0.0f, Ev = 0.0f;
    if (d < 5) {
        int j = i + d - 2;
        if (j >= 0 && j < l) {
            float Mv = 1.0f - s[d + 1] * invnx * sh_invny[w + d];
            Kv = __expf(-LAMf * Mv);
            Ev = Kv * Mv;
        }
    }
    float S = Kv, E = Ev;
    #pragma unroll
    for (int o = 4; o; o >>= 1) {
        S += __shfl_xor_sync(0xffffffffu, S, o);
        E += __shfl_xor_sync(0xffffffffu, E, o);
    }
    float invS = 1.0f / S;
    int rr = base + i;
    if (lane < 5) g_Kn[rr*5 + lane] = Kv * invS;
    if (lane == 0) g_En[rr] = E * invS;
}

// ---------------------------------------------------------------- t + cost + band scatter (verified)
__global__ void __launch_bounds__(1024) ktc(const int* __restrict__ lengths,
                                            float* __restrict__ out) {
    __shared__ float sh_K[Lr*5];
    __shared__ float sh_t[Lr];
    __shared__ float sh_c[Lr];
    int b = blockIdx.x;
    int j = threadIdx.x;
    int l = lengths[b];
    int base = b * Lr;

    float Ev = g_En[base + j];
    {
        const float4* Ksrc = (const float4*)(g_Kn + (size_t)base * 5);
        float4* Kdst = (float4*)sh_K;
        #pragma unroll
        for (int k = 0; k < 2; k++)
            if (j + k*1024 < Lr*5/4) Kdst[j + k*1024] = Ksrc[j + k*1024];
    }
    __syncthreads();

    float t = 1.0f, term = 0.0f;
    if (j < l) {
        t = 0.0f;
        #pragma unroll
        for (int dd = 0; dd < 5; dd++) {
            int i = j + dd - 2;
            if (i >= 0 && i < l)
                t += sh_K[i*5 + (4 - dd)];
        }
        term = Ev / ((float)l * t);
    }
    sh_t[j] = t;
    sh_c[j] = term;
    __syncthreads();

    if (j < l) {
        float rt = 1.0f / sh_t[j];
        float* Po = out + (size_t)b * Lr * Lr + (size_t)j * Lr;
        #pragma unroll
        for (int dd = 0; dd < 5; dd++) {
            int jj = j + dd - 2;
            if (jj >= 0 && jj < l)
                Po[jj] = sh_K[j*5 + dd] * sh_t[jj] * rt;
        }
    }

    #pragma unroll
    for (int s = 512; s; s >>= 1) {
        if (j < s) sh_c[j] += sh_c[j + s];
        __syncthreads();
    }
    if (j == 0) out[(size_t)Br * Lr * Lr + b] = sh_c[0];
}

extern "C" void kernel_launch(void* const* d_in, const int* in_sizes, int n_in,
                              void* d_out, int out_size) {
    const float* m1      = (const float*)d_in[0];
    const float* m2      = (const float*)d_in[1];
    const int*   lengths = (const int*)d_in[2];
    float* out = (float*)d_out;

    kband<<<Br*64, 512>>>(m1, m2, lengths);   // smem-staged y tiles
    ktc<<<Br, 1024>>>(lengths, out);          // verified epilogue
}

// round 16
// speedup vs baseline: 1.1001x; 1.1001x over previous
#include <cuda_runtime.h>
#include <math.h>

#define Lr 1024
#define Br 32
#define Dr 256
#define LAMf 0.2f
#define NR (Lr*Br)

// Scratch (device globals, zero-initialized). Batch-major r = b*Lr + i.
__device__ float g_Kn[NR*5];     // K[i,d] * invS[i]
__device__ float g_En[NR];       // E[i]  * invS[i]

typedef unsigned long long u64;

__device__ __forceinline__ u64 ffma2(u64 a, u64 b, u64 c) {
    u64 d;
    asm("fma.rn.f32x2 %0, %1, %2, %3;" : "=l"(d) : "l"(a), "l"(b), "l"(c));
    return d;
}
__device__ __forceinline__ float unpack_sum(u64 a) {
    float2 f = *reinterpret_cast<float2*>(&a);
    return f.x + f.y;
}

// ---------------------------------------------------------------- band kernel
// 2048 batch-pure blocks x 256 threads; warp w owns rows i = i0+2w and i+1.
// 6 shared y loads serve both rows' 10 dots; y-norms of own rows ride in the
// butterfly; 4 edge-row norms via mini-pass; lane-parallel two-group tail.
__global__ void __launch_bounds__(256) kband(const float* __restrict__ m1,
                                             const float* __restrict__ m2,
                                             const int* __restrict__ lengths) {
    __shared__ float sh_invny[20];   // 1/||y_{i0-2+k}||, k = 0..19

    int tid  = threadIdx.x;
    int w    = tid >> 5, lane = tid & 31;
    int b    = blockIdx.x & 31;
    int i0   = (blockIdx.x >> 5) * 16;
    int l    = __ldg(lengths + b);
    int base = b * Lr;
    int i    = i0 + 2*w;                   // rows i, i+1
    bool v0  = (i < l), v1 = (i + 1 < l);

    // acc: 0=xx0 1=xx1 2=yy(i) 3=yy(i+1) 4..8=dots row i (d=0..4) 9..13=dots row i+1
    u64 acc[14];
    #pragma unroll
    for (int q = 0; q < 14; q++) acc[q] = 0ull;

    ulonglong2 x0a, x0b, x1a, x1b;
    x0a.x=x0a.y=x0b.x=x0b.y=0ull;
    x1a.x=x1a.y=x1b.x=x1b.y=0ull;
    if (v0) {
        const ulonglong2* xp = (const ulonglong2*)(m1 + ((size_t)(i*Br + b)) * Dr);
        x0a = xp[lane]; x0b = xp[lane + 32];
        acc[0] = ffma2(x0a.x, x0a.x, 0ull);
        acc[0] = ffma2(x0a.y, x0a.y, acc[0]);
        acc[0] = ffma2(x0b.x, x0b.x, acc[0]);
        acc[0] = ffma2(x0b.y, x0b.y, acc[0]);
    }
    if (v1) {
        const ulonglong2* xp = (const ulonglong2*)(m1 + ((size_t)((i+1)*Br + b)) * Dr);
        x1a = xp[lane]; x1b = xp[lane + 32];
        acc[1] = ffma2(x1a.x, x1a.x, 0ull);
        acc[1] = ffma2(x1a.y, x1a.y, acc[1]);
        acc[1] = ffma2(x1b.x, x1b.x, acc[1]);
        acc[1] = ffma2(x1b.y, x1b.y, acc[1]);
    }

    // 6 y rows jr = i-2+k serve row i (k<=4 -> d=k) and row i+1 (k>=1 -> d=k-1)
    #pragma unroll
    for (int k = 0; k < 6; k++) {
        int jr = i - 2 + k;
        if (jr >= 0 && jr < l) {
            const ulonglong2* yp = (const ulonglong2*)(m2 + ((size_t)(jr*Br + b)) * Dr);
            ulonglong2 ya = yp[lane], yb = yp[lane + 32];
            if (k <= 4) {
                u64 a = ffma2(x0a.x, ya.x, 0ull);
                a = ffma2(x0a.y, ya.y, a);
                a = ffma2(x0b.x, yb.x, a);
                a = ffma2(x0b.y, yb.y, a);
                acc[4 + k] = a;
            }
            if (k >= 1) {
                u64 a = ffma2(x1a.x, ya.x, 0ull);
                a = ffma2(x1a.y, ya.y, a);
                a = ffma2(x1b.x, yb.x, a);
                a = ffma2(x1b.y, yb.y, a);
                acc[9 + k - 1] = a;
            }
            if (k == 2 || k == 3) {
                u64 yy = ffma2(ya.x, ya.x, 0ull);
                yy = ffma2(ya.y, ya.y, yy);
                yy = ffma2(yb.x, yb.x, yy);
                yy = ffma2(yb.y, yb.y, yy);
                acc[k] = yy;                 // slots 2, 3
            }
        }
    }

    float s[14];
    #pragma unroll
    for (int q = 0; q < 14; q++) s[q] = unpack_sum(acc[q]);
    #pragma unroll
    for (int o = 16; o; o >>= 1) {
        #pragma unroll
        for (int q = 0; q < 14; q++) s[q] += __shfl_xor_sync(0xffffffffu, s[q], o);
    }
    if (lane == 0) {
        if (v0) sh_invny[2*w + 2] = 1.0f / fmaxf(sqrtf(s[2]), 1e-5f);   // j = i
        if (v1) sh_invny[2*w + 3] = 1.0f / fmaxf(sqrtf(s[3]), 1e-5f);   // j = i+1
    }

    // ---- mini-pass: 4 edge y-norm rows (slots 0,1,18,19) by warps 0-3 ----
    if (w < 4) {
        int eidx = (w < 2) ? w : (16 + w);
        int row  = i0 - 2 + eidx;
        float ss = 0.0f;
        if (row >= 0 && row < l) {
            const ulonglong2* p = (const ulonglong2*)(m2 + ((size_t)(row*Br + b)) * Dr);
            ulonglong2 a = p[lane], c = p[lane + 32];
            u64 q = ffma2(a.x, a.x, 0ull);
            q = ffma2(a.y, a.y, q);
            q = ffma2(c.x, c.x, q);
            q = ffma2(c.y, c.y, q);
            ss = unpack_sum(q);
        }
        #pragma unroll
        for (int o = 16; o; o >>= 1) ss += __shfl_xor_sync(0xffffffffu, ss, o);
        if (lane == 0)
            sh_invny[eidx] = (ss > 0.0f) ? (1.0f / fmaxf(sqrtf(ss), 1e-5f)) : 0.0f;
    }
    __syncthreads();

    // ---- lane-parallel tail: lanes 0-7 = row i, lanes 8-15 = row i+1 ----
    int sel = (lane >> 3) & 1;
    int d   = lane & 7;
    int r   = i + sel;
    float Kv = 0.0f, Ev = 0.0f;
    if (lane < 16 && d < 5 && r < l) {
        int j = r + d - 2;
        if (j >= 0 && j < l) {
            float invnx = 1.0f / fmaxf(sqrtf(s[sel]), 1e-5f);
            float Mv = 1.0f - s[(sel ? 9 : 4) + d] * invnx * sh_invny[2*w + sel + d];
            Kv = __expf(-LAMf * Mv);
            Ev = Kv * Mv;
        }
    }
    float S = Kv, E = Ev;
    #pragma unroll
    for (int o = 4; o; o >>= 1) {              // sums within each 8-lane group
        S += __shfl_xor_sync(0xffffffffu, S, o);
        E += __shfl_xor_sync(0xffffffffu, E, o);
    }
    if (lane < 16 && r < l) {
        float invS = 1.0f / S;
        if (d < 5) g_Kn[(size_t)(base + r)*5 + d] = Kv * invS;
        if (d == 0) g_En[base + r] = E * invS;
    }
}

// ---------------------------------------------------------------- t + cost + band scatter (verified)
__global__ void __launch_bounds__(1024) ktc(const int* __restrict__ lengths,
                                            float* __restrict__ out) {
    __shared__ float sh_K[Lr*5];
    __shared__ float sh_t[Lr];
    __shared__ float sh_c[Lr];
    int b = blockIdx.x;
    int j = threadIdx.x;
    int l = lengths[b];
    int base = b * Lr;

    float Ev = g_En[base + j];
    {
        const float4* Ksrc = (const float4*)(g_Kn + (size_t)base * 5);
        float4* Kdst = (float4*)sh_K;
        #pragma unroll
        for (int k = 0; k < 2; k++)
            if (j + k*1024 < Lr*5/4) Kdst[j + k*1024] = Ksrc[j + k*1024];
    }
    __syncthreads();

    float t = 1.0f, term = 0.0f;
    if (j < l) {
        t = 0.0f;
        #pragma unroll
        for (int dd = 0; dd < 5; dd++) {
            int i = j + dd - 2;
            if (i >= 0 && i < l)
                t += sh_K[i*5 + (4 - dd)];
        }
        term = Ev / ((float)l * t);
    }
    sh_t[j] = t;
    sh_c[j] = term;
    __syncthreads();

    if (j < l) {
        float rt = 1.0f / sh_t[j];
        float* Po = out + (size_t)b * Lr * Lr + (size_t)j * Lr;
        #pragma unroll
        for (int dd = 0; dd < 5; dd++) {
            int jj = j + dd - 2;
            if (jj >= 0 && jj < l)
                Po[jj] = sh_K[j*5 + dd] * sh_t[jj] * rt;
        }
    }

    #pragma unroll
    for (int s = 512; s; s >>= 1) {
        if (j < s) sh_c[j] += sh_c[j + s];
        __syncthreads();
    }
    if (j == 0) out[(size_t)Br * Lr * Lr + b] = sh_c[0];
}

extern "C" void kernel_launch(void* const* d_in, const int* in_sizes, int n_in,
                              void* d_out, int out_size) {
    const float* m1      = (const float*)d_in[0];
    const float* m2      = (const float*)d_in[1];
    const int*   lengths = (const int*)d_in[2];
    float* out = (float*)d_out;

    kband<<<Br*64, 256>>>(m1, m2, lengths);   // 2 rows/warp, shared y loads
    ktc<<<Br, 1024>>>(lengths, out);          // verified epilogue
}